// round 17
// baseline (speedup 1.0000x reference)
#include <cuda_runtime.h>

#define VDIM 256
#define VSLICE (256L * 256L * 256L)

// ---------------------------------------------------------------------------
// L2 policy helpers.
// ---------------------------------------------------------------------------
__device__ __forceinline__ unsigned long long policy_evict_last() {
    unsigned long long p;
    asm("createpolicy.fractional.L2::evict_last.b64 %0, 1.0;" : "=l"(p));
    return p;
}
__device__ __forceinline__ unsigned long long policy_evict_first() {
    unsigned long long p;
    asm("createpolicy.fractional.L2::evict_first.b64 %0, 1.0;" : "=l"(p));
    return p;
}

// 256-bit streaming load: 8 floats, 32B-aligned.
__device__ __forceinline__ void ldg_v8(const float* p, float* v,
                                       unsigned long long pol) {
    unsigned r0, r1, r2, r3, r4, r5, r6, r7;
    asm("ld.global.nc.L2::cache_hint.v8.b32 {%0,%1,%2,%3,%4,%5,%6,%7}, [%8], %9;"
        : "=r"(r0), "=r"(r1), "=r"(r2), "=r"(r3),
          "=r"(r4), "=r"(r5), "=r"(r6), "=r"(r7)
        : "l"(p), "l"(pol));
    v[0] = __uint_as_float(r0); v[1] = __uint_as_float(r1);
    v[2] = __uint_as_float(r2); v[3] = __uint_as_float(r3);
    v[4] = __uint_as_float(r4); v[5] = __uint_as_float(r5);
    v[6] = __uint_as_float(r6); v[7] = __uint_as_float(r7);
}

__device__ __forceinline__ void red_f32(float* a, float x, unsigned long long pol) {
    asm volatile("red.global.add.L2::cache_hint.f32 [%0], %1, %2;"
                 :: "l"(a), "f"(x), "l"(pol) : "memory");
}
__device__ __forceinline__ void red_v2(float* a, float x, float y, unsigned long long pol) {
    asm volatile("red.global.add.L2::cache_hint.v2.f32 [%0], {%1,%2}, %3;"
                 :: "l"(a), "f"(x), "f"(y), "l"(pol) : "memory");
}
__device__ __forceinline__ void red_v4(float* a, float x, float y, float z, float w,
                                       unsigned long long pol) {
    asm volatile("red.global.add.L2::cache_hint.v4.f32 [%0], {%1,%2,%3,%4}, %5;"
                 :: "l"(a), "f"(x), "f"(y), "f"(z), "f"(w), "l"(pol) : "memory");
}

// ---------------------------------------------------------------------------
// Zero-init: one 256-bit store per thread, installed as evict_last.
// ---------------------------------------------------------------------------
__global__ void zero_kernel(float* __restrict__ out, long n) {
    long i = (long)(blockIdx.x * blockDim.x + threadIdx.x) * 8;
    if (i < n) {
        unsigned long long pol = policy_evict_last();
        asm volatile("st.global.L2::cache_hint.v8.b32 [%0], "
                     "{%1,%1,%1,%1,%1,%1,%1,%1}, %2;"
                     :: "l"(out + i), "r"(0u), "l"(pol) : "memory");
    }
}

// ---------------------------------------------------------------------------
// Splat one point (R10 request-minimal encoding, 5 req/pt avg — proven floor):
//   even ix       -> 4x red.v2
//   ix%4 in {1,2} -> 4x padded red.v4 (zero lanes free; requests rule)
//   ix%4 == 3     -> 8x scalar red (pair straddles the 16B quad)
// ---------------------------------------------------------------------------
__device__ __forceinline__ void splat_one(float x, float y, float z, float f,
                                          float* __restrict__ out,
                                          unsigned long long pol) {
    float fx = (x + 1.0f) * 127.5f;
    float fy = (y + 1.0f) * 127.5f;
    float fz = (z + 1.0f) * 127.5f;

    float lx = floorf(fx), ly = floorf(fy), lz = floorf(fz);
    int ix = (int)lx, iy = (int)ly, iz = (int)lz;
    float tx = fx - lx, ty = fy - ly, tz = fz - lz;

    if ((unsigned)ix < 255u && (unsigned)iy < 255u && (unsigned)iz < 255u) {
        float ax = 1.0f - tx;
        float w[4];
        w[0] = (1.0f - ty) * (1.0f - tz) * f;   // (iy,   iz)
        w[1] = ty * (1.0f - tz) * f;            // (iy+1, iz)
        w[2] = (1.0f - ty) * tz * f;            // (iy,   iz+1)
        w[3] = ty * tz * f;                     // (iy+1, iz+1)
        const long roff[4] = {0L, VDIM, (long)VDIM * VDIM, (long)VDIM * VDIM + VDIM};

        float* rowbase = out + (((long)iz * VDIM + iy) * VDIM);
        int off = ix & 3;

        if ((ix & 1) == 0) {
            #pragma unroll
            for (int c = 0; c < 4; c++)
                red_v2(rowbase + roff[c] + ix, w[c] * ax, w[c] * tx, pol);
        } else if (off != 3) {
            int ixa = ix & ~3;
            #pragma unroll
            for (int c = 0; c < 4; c++)
                red_v4(rowbase + roff[c] + ixa, 0.0f, w[c] * ax, w[c] * tx, 0.0f, pol);
        } else {
            #pragma unroll
            for (int c = 0; c < 4; c++) {
                red_f32(rowbase + roff[c] + ix,     w[c] * ax, pol);
                red_f32(rowbase + roff[c] + ix + 1, w[c] * tx, pol);
            }
        }
    } else {
        // Exact reference semantics for boundary / out-of-range points.
        #pragma unroll
        for (int dz = 0; dz < 2; dz++)
        #pragma unroll
        for (int dy = 0; dy < 2; dy++)
        #pragma unroll
        for (int dx = 0; dx < 2; dx++) {
            int jx = ix + dx, jy = iy + dy, jz = iz + dz;
            float wq = (dx ? tx : 1.0f - tx) *
                       (dy ? ty : 1.0f - ty) *
                       (dz ? tz : 1.0f - tz) * f;
            if (jx >= 0 && jx < VDIM && jy >= 0 && jy < VDIM &&
                jz >= 0 && jz < VDIM) {
                atomicAdd(out + (((long)jz * VDIM + jy) * VDIM + jx), wq);
            }
        }
    }
}

// ---------------------------------------------------------------------------
// Per-phase splat: 8 points/thread via 4x 256-bit loads (3 pts + 1 feat).
// Offsets: pts + 24*t floats = 96B*t (32B-aligned), feat + 8*t = 32B*t.
// ---------------------------------------------------------------------------
__global__ void splat_kernel(const float* __restrict__ pts,
                             const float* __restrict__ feat,
                             float* __restrict__ out,
                             float scale, int total) {
    long t = blockIdx.x * blockDim.x + threadIdx.x;
    long p0 = t * 8;
    if (p0 >= total) return;

    unsigned long long polL = policy_evict_last();
    unsigned long long polF = policy_evict_first();

    if (p0 + 7 < total) {
        float v[24], ff[8];
        ldg_v8(pts + p0 * 3,      v,      polF);
        ldg_v8(pts + p0 * 3 + 8,  v + 8,  polF);
        ldg_v8(pts + p0 * 3 + 16, v + 16, polF);
        ldg_v8(feat + p0,         ff,     polF);
        #pragma unroll
        for (int k = 0; k < 8; k++)
            splat_one(v[3 * k], v[3 * k + 1], v[3 * k + 2],
                      ff[k] * scale, out, polL);
    } else {
        for (long p = p0; p < total; p++) {
            splat_one(pts[3 * p], pts[3 * p + 1], pts[3 * p + 2],
                      feat[p] * scale, out, polL);
        }
    }
}

// ---------------------------------------------------------------------------
// kernel_launch: zero0 -> splatA(slice0) -> zero1 -> splatB(slice1).
// ---------------------------------------------------------------------------
extern "C" void kernel_launch(void* const* d_in, const int* in_sizes, int n_in,
                              void* d_out, int out_size) {
    const float* pts  = (const float*)d_in[0];
    const float* feat = (const float*)d_in[1];
    float* out = (float*)d_out;

    int BP = in_sizes[1];   // 3 * P
    int P  = BP / 3;

    long nslice = VSLICE;                       // floats per slice
    int zthreads = (int)((nslice + 7) / 8);

    // Phase A: slice 0 (views 0,1; scale 0.5 folds the 2-view mean).
    zero_kernel<<<(zthreads + 255) / 256, 256>>>(out, nslice);
    int totalA = 2 * P;
    int tA = (totalA + 7) / 8;
    splat_kernel<<<(tA + 255) / 256, 256>>>(pts, feat, out, 0.5f, totalA);

    // Phase B: slice 1 (view 2).
    float* out1 = out + VSLICE;
    zero_kernel<<<(zthreads + 255) / 256, 256>>>(out1, nslice);
    const float* ptsB  = pts + 3L * (long)(2 * P);
    const float* featB = feat + 2L * (long)P;
    int tB = (P + 7) / 8;
    splat_kernel<<<(tB + 255) / 256, 256>>>(ptsB, featB, out1, 1.0f, P);
}